// round 1
// baseline (speedup 1.0000x reference)
#include <cuda_runtime.h>

#define BB 256
#define TT 64
#define IN 512
#define HH 1024
#define NS (BB*TT)   /* 16384 samples, s = t*B + b */

// ---------------- scratch (__device__ globals; no allocs allowed) ----------------
__device__ unsigned int g_maskX[NS*16];        // 512-bit mask per sample
__device__ unsigned int g_mask0[NS*32];        // 1024-bit mask per sample
__device__ unsigned int g_mask1[NS*32];
__device__ float g_cur0[(size_t)NS*HH];        // 64 MB
__device__ float g_cur1[(size_t)NS*HH];        // 64 MB
__device__ float g_cur2[NS*2];
__device__ float g_W0t[IN*HH];                 // W0^T : [512][1024]
__device__ float g_W1t[HH*HH];                 // W1^T : [1024][1024]
__device__ float g_W2t[HH*2];                  // W2^T : [1024][2]

// ---------------- transpose: in[R][C] -> out[C][R] ----------------
__global__ void k_transpose(const float* __restrict__ in, float* __restrict__ out,
                            int R, int C) {
    __shared__ float tl[32][33];
    int c0 = blockIdx.x * 32, r0 = blockIdx.y * 32;
    int x = c0 + threadIdx.x;
    for (int j = 0; j < 32; j += 8) {
        int y = r0 + threadIdx.y + j;
        if (y < R && x < C) tl[threadIdx.y + j][threadIdx.x] = in[(size_t)y * C + x];
    }
    __syncthreads();
    int x2 = r0 + threadIdx.x;
    for (int j = 0; j < 32; j += 8) {
        int y2 = c0 + threadIdx.y + j;
        if (y2 < C && x2 < R) out[(size_t)y2 * R + x2] = tl[threadIdx.x][threadIdx.y + j];
    }
}

// ---------------- pack x [B,T,I] (batch-first) -> bitmask [s=(t*B+b)][16 words] ----
__global__ void k_pack_x(const float* __restrict__ x, unsigned int* __restrict__ mx) {
    int idx = blockIdx.x * blockDim.x + threadIdx.x;   // NS*IN threads
    int i = idx & (IN - 1);
    int s = idx >> 9;
    int t = s >> 8;          // s = t*B + b, B=256
    int b = s & (BB - 1);
    float v = x[((size_t)b * TT + t) * IN + i];
    unsigned bal = __ballot_sync(0xffffffffu, v != 0.0f);
    if ((i & 31) == 0) mx[s * 16 + (i >> 5)] = bal;
}

// ---------------- sparse binary GEMM: cur[s][h] = sum_{k: bit set} Wt[k][h] -------
// S samples per CTA share a [KT x HT] smem weight tile; k-skip is CTA-uniform.
#define S  64
#define HT 256
#define KT 32

__global__ __launch_bounds__(256, 2)
void k_gemm_sparse(const unsigned int* __restrict__ masks,
                   const float* __restrict__ Wt,
                   float* __restrict__ cur, int KW /* = K/32 words */) {
    __shared__ float tile[KT * HT];
    __shared__ unsigned int smask[S];
    int tid = threadIdx.x;
    int s0 = blockIdx.x * S;
    int hbase = blockIdx.y * HT;

    float acc[S];
#pragma unroll
    for (int s = 0; s < S; ++s) acc[s] = 0.0f;

    for (int tw = 0; tw < KW; ++tw) {
        __syncthreads();                       // protect tile/smask from prev iter readers
        if (tid < S) smask[tid] = masks[(size_t)(s0 + tid) * KW + tw];
        __syncthreads();

        unsigned int U = 0;                    // union of this k-tile's bits (uniform)
#pragma unroll 8
        for (int j = 0; j < S; ++j) U |= smask[j];

        if (U) {
            const float* Wbase = Wt + (size_t)(tw * KT) * HH + hbase;
            unsigned int u = U;                // load only rows that any sample needs
            while (u) {
                int r = __ffs(u) - 1; u &= u - 1;
                tile[r * HT + tid] = Wbase[(size_t)r * HH + tid];
            }
            __syncthreads();
#pragma unroll
            for (int s = 0; s < S; ++s) {
                unsigned int m = smask[s];
                while (m) {
                    int k = __ffs(m) - 1; m &= m - 1;
                    acc[s] += tile[k * HT + tid];
                }
            }
        }
    }
    int h = hbase + tid;
#pragma unroll
    for (int s = 0; s < S; ++s) cur[(size_t)(s0 + s) * HH + h] = acc[s];
}

// ---------------- tiny output layer GEMM (H=2) ----------------
__global__ void k_gemm2(const unsigned int* __restrict__ masks,
                        const float* __restrict__ W2t, float* __restrict__ cur2) {
    int s = blockIdx.x * blockDim.x + threadIdx.x;
    if (s >= NS) return;
    float a0 = 0.0f, a1 = 0.0f;
    for (int w = 0; w < 32; ++w) {
        unsigned int m = masks[(size_t)s * 32 + w];
        while (m) {
            int k = __ffs(m) - 1; m &= m - 1;
            int kk = w * 32 + k;
            a0 += W2t[kk * 2];
            a1 += W2t[kk * 2 + 1];
        }
    }
    cur2[s * 2] = a0;
    cur2[s * 2 + 1] = a1;
}

// ---------------- leaky membrane scan over time (elementwise per (b,h)) ----------
__global__ void k_scan(const float* __restrict__ cur, const float* __restrict__ thr_p,
                       float* __restrict__ spk_out, float* __restrict__ mem_out,
                       unsigned int* __restrict__ mask_out, int Hdim) {
    int h = blockIdx.x * blockDim.x + threadIdx.x;
    int b = blockIdx.y;
    if (h >= Hdim) return;
    float thr = *thr_p;
    float mem = 0.0f;
    for (int t = 0; t < TT; ++t) {
        size_t idx = ((size_t)t * BB + b) * Hdim + h;
        float reset = (mem > thr) ? thr : 0.0f;        // uses mem from previous step
        mem = 0.5f * mem + cur[idx] - reset;
        float spk = (mem - thr) > 0.0f ? 1.0f : 0.0f;  // atan_spike forward = Heaviside
        spk_out[idx] = spk;
        mem_out[idx] = mem;
        if (mask_out) {
            unsigned bal = __ballot_sync(0xffffffffu, spk != 0.0f);
            if ((h & 31) == 0)
                mask_out[((size_t)t * BB + b) * (Hdim >> 5) + (h >> 5)] = bal;
        }
    }
}

// ---------------- launch ----------------
extern "C" void kernel_launch(void* const* d_in, const int* in_sizes, int n_in,
                              void* d_out, int out_size) {
    const float* x    = (const float*)d_in[0];
    const float* W0   = (const float*)d_in[1];
    const float* W1   = (const float*)d_in[2];
    const float* W2   = (const float*)d_in[3];
    const float* thr0 = (const float*)d_in[4];
    const float* thr1 = (const float*)d_in[5];
    const float* thr2 = (const float*)d_in[6];
    float* out = (float*)d_out;

    float *W0t, *W1t, *W2t, *cur0, *cur1, *cur2;
    unsigned int *maskX, *mask0, *mask1;
    cudaGetSymbolAddress((void**)&W0t,   g_W0t);
    cudaGetSymbolAddress((void**)&W1t,   g_W1t);
    cudaGetSymbolAddress((void**)&W2t,   g_W2t);
    cudaGetSymbolAddress((void**)&cur0,  g_cur0);
    cudaGetSymbolAddress((void**)&cur1,  g_cur1);
    cudaGetSymbolAddress((void**)&cur2,  g_cur2);
    cudaGetSymbolAddress((void**)&maskX, g_maskX);
    cudaGetSymbolAddress((void**)&mask0, g_mask0);
    cudaGetSymbolAddress((void**)&mask1, g_mask1);

    // output layout: spk0, spk1, spk2, mem0, mem1, mem2
    float* spk0 = out;
    float* spk1 = spk0 + (size_t)NS * HH;
    float* spk2 = spk1 + (size_t)NS * HH;
    float* mem0 = spk2 + (size_t)NS * 2;
    float* mem1 = mem0 + (size_t)NS * HH;
    float* mem2 = mem1 + (size_t)NS * HH;

    // weight transposes (K-major for row-gather)
    k_transpose<<<dim3(IN/32, HH/32), dim3(32, 8)>>>(W0, W0t, HH, IN);
    k_transpose<<<dim3(HH/32, HH/32), dim3(32, 8)>>>(W1, W1t, HH, HH);
    k_transpose<<<dim3(HH/32, 1),     dim3(32, 8)>>>(W2, W2t, 2,  HH);

    // pack input spikes to bitmasks (also does [B,T]->[T,B] reindex)
    k_pack_x<<<(NS * IN) / 256, 256>>>(x, maskX);

    // layer 0
    k_gemm_sparse<<<dim3(NS/S, HH/HT), 256>>>(maskX, W0t, cur0, IN/32);
    k_scan<<<dim3(HH/256, BB), 256>>>(cur0, thr0, spk0, mem0, mask0, HH);

    // layer 1
    k_gemm_sparse<<<dim3(NS/S, HH/HT), 256>>>(mask0, W1t, cur1, HH/32);
    k_scan<<<dim3(HH/256, BB), 256>>>(cur1, thr1, spk1, mem1, mask1, HH);

    // layer 2
    k_gemm2<<<NS/256, 256>>>(mask1, W2t, cur2);
    k_scan<<<dim3(1, BB), 32>>>(cur2, thr2, spk2, mem2, (unsigned int*)0, 2);
}

// round 2
// speedup vs baseline: 1.4917x; 1.4917x over previous
#include <cuda_runtime.h>

#define BB 256
#define TT 64
#define IN 512
#define HH 1024
#define NS (BB*TT)   /* 16384 samples, s = t*B + b */

// ---------------- scratch (__device__ globals; no allocs allowed) ----------------
__device__ unsigned int g_maskX[NS*16];        // 512-bit mask per sample
__device__ unsigned int g_mask0[NS*32];        // 1024-bit mask per sample
__device__ unsigned int g_mask1[NS*32];
__device__ float g_cur0[(size_t)NS*HH];        // 64 MB
__device__ float g_cur1[(size_t)NS*HH];        // 64 MB
__device__ float g_cur2[NS*2];
__device__ float g_W0t[IN*HH];                 // W0^T : [512][1024]
__device__ float g_W1t[HH*HH];                 // W1^T : [1024][1024]
__device__ float g_W2t[HH*2];                  // W2^T : [1024][2]

// ---------------- transpose: in[R][C] -> out[C][R] ----------------
__global__ void k_transpose(const float* __restrict__ in, float* __restrict__ out,
                            int R, int C) {
    __shared__ float tl[32][33];
    int c0 = blockIdx.x * 32, r0 = blockIdx.y * 32;
    int x = c0 + threadIdx.x;
    for (int j = 0; j < 32; j += 8) {
        int y = r0 + threadIdx.y + j;
        if (y < R && x < C) tl[threadIdx.y + j][threadIdx.x] = in[(size_t)y * C + x];
    }
    __syncthreads();
    int x2 = r0 + threadIdx.x;
    for (int j = 0; j < 32; j += 8) {
        int y2 = c0 + threadIdx.y + j;
        if (y2 < C && x2 < R) out[(size_t)y2 * R + x2] = tl[threadIdx.x][threadIdx.y + j];
    }
}

// ---------------- pack x [B,T,I] (batch-first) -> bitmask [s=(t*B+b)][16 words] ----
__global__ void k_pack_x(const float* __restrict__ x, unsigned int* __restrict__ mx) {
    int idx = blockIdx.x * blockDim.x + threadIdx.x;   // NS*IN threads
    int i = idx & (IN - 1);
    int s = idx >> 9;
    int t = s >> 8;          // s = t*B + b, B=256
    int b = s & (BB - 1);
    float v = x[((size_t)b * TT + t) * IN + i];
    unsigned bal = __ballot_sync(0xffffffffu, v != 0.0f);
    if ((i & 31) == 0) mx[s * 16 + (i >> 5)] = bal;
}

// ---------------- sparse binary GEMM (float4 per thread, full H per CTA) ----------
// cur[s][h] = sum_{k: bit set} Wt[k][h].  S samples per CTA share a [KT x H]
// dynamic-smem weight tile; k-skip and all branches are CTA-uniform.
#define S3 32
#define KT 32

extern __shared__ float dyn_tile[];   // KT * HH floats = 128 KB

__global__ __launch_bounds__(256, 1)
void k_gemm_sparse4(const unsigned int* __restrict__ masks,
                    const float* __restrict__ Wt,
                    float* __restrict__ cur, int KW /* = K/32 words */) {
    __shared__ unsigned int smask[S3];
    int tid = threadIdx.x;
    int s0 = blockIdx.x * S3;
    int c4 = tid * 4;                  // this thread's 4 h-columns

    float4 acc[S3];
#pragma unroll
    for (int s = 0; s < S3; ++s) acc[s] = make_float4(0.f, 0.f, 0.f, 0.f);

    for (int tw = 0; tw < KW; ++tw) {
        __syncthreads();                       // protect tile/smask from prev readers
        if (tid < S3) smask[tid] = masks[(size_t)(s0 + tid) * KW + tw];
        __syncthreads();

        unsigned int U = 0;                    // union of this k-tile's bits (uniform)
#pragma unroll
        for (int j = 0; j < S3; ++j) U |= smask[j];
        if (!U) continue;

        {   // stage only the rows any sample needs (uniform ffs loop)
            const float* Wb = Wt + (size_t)(tw * KT) * HH + c4;
            unsigned int u = U;
            while (u) {
                int r = __ffs(u) - 1; u &= u - 1;
                float4 w = *(const float4*)(Wb + (size_t)r * HH);
                *(float4*)&dyn_tile[r * HH + c4] = w;
            }
        }
        __syncthreads();

#pragma unroll
        for (int s = 0; s < S3; ++s) {
            unsigned int m = smask[s];
            while (m) {
                int k = __ffs(m) - 1; m &= m - 1;
                float4 w = *(const float4*)&dyn_tile[k * HH + c4];
                acc[s].x += w.x; acc[s].y += w.y; acc[s].z += w.z; acc[s].w += w.w;
            }
        }
    }
#pragma unroll
    for (int s = 0; s < S3; ++s)
        *(float4*)&cur[(size_t)(s0 + s) * HH + c4] = acc[s];
}

// ---------------- tiny output layer GEMM (H=2) ----------------
__global__ void k_gemm2(const unsigned int* __restrict__ masks,
                        const float* __restrict__ W2t, float* __restrict__ cur2) {
    int s = blockIdx.x * blockDim.x + threadIdx.x;
    if (s >= NS) return;
    float a0 = 0.0f, a1 = 0.0f;
    for (int w = 0; w < 32; ++w) {
        unsigned int m = masks[(size_t)s * 32 + w];
        while (m) {
            int k = __ffs(m) - 1; m &= m - 1;
            int kk = w * 32 + k;
            a0 += W2t[kk * 2];
            a1 += W2t[kk * 2 + 1];
        }
    }
    cur2[s * 2] = a0;
    cur2[s * 2 + 1] = a1;
}

// ---------------- leaky membrane scan over time (elementwise per (b,h)) ----------
__global__ void k_scan(const float* __restrict__ cur, const float* __restrict__ thr_p,
                       float* __restrict__ spk_out, float* __restrict__ mem_out,
                       unsigned int* __restrict__ mask_out, int Hdim) {
    int h = blockIdx.x * blockDim.x + threadIdx.x;
    int b = blockIdx.y;
    if (h >= Hdim) return;
    float thr = *thr_p;
    float mem = 0.0f;
    for (int t = 0; t < TT; ++t) {
        size_t idx = ((size_t)t * BB + b) * Hdim + h;
        float reset = (mem > thr) ? thr : 0.0f;        // uses mem from previous step
        mem = 0.5f * mem + cur[idx] - reset;
        float spk = (mem - thr) > 0.0f ? 1.0f : 0.0f;  // atan_spike forward = Heaviside
        spk_out[idx] = spk;
        mem_out[idx] = mem;
        if (mask_out) {
            unsigned bal = __ballot_sync(0xffffffffu, spk != 0.0f);
            if ((h & 31) == 0)
                mask_out[((size_t)t * BB + b) * (Hdim >> 5) + (h >> 5)] = bal;
        }
    }
}

// ---------------- launch ----------------
extern "C" void kernel_launch(void* const* d_in, const int* in_sizes, int n_in,
                              void* d_out, int out_size) {
    const float* x    = (const float*)d_in[0];
    const float* W0   = (const float*)d_in[1];
    const float* W1   = (const float*)d_in[2];
    const float* W2   = (const float*)d_in[3];
    const float* thr0 = (const float*)d_in[4];
    const float* thr1 = (const float*)d_in[5];
    const float* thr2 = (const float*)d_in[6];
    float* out = (float*)d_out;

    float *W0t, *W1t, *W2t, *cur0, *cur1, *cur2;
    unsigned int *maskX, *mask0, *mask1;
    cudaGetSymbolAddress((void**)&W0t,   g_W0t);
    cudaGetSymbolAddress((void**)&W1t,   g_W1t);
    cudaGetSymbolAddress((void**)&W2t,   g_W2t);
    cudaGetSymbolAddress((void**)&cur0,  g_cur0);
    cudaGetSymbolAddress((void**)&cur1,  g_cur1);
    cudaGetSymbolAddress((void**)&cur2,  g_cur2);
    cudaGetSymbolAddress((void**)&maskX, g_maskX);
    cudaGetSymbolAddress((void**)&mask0, g_mask0);
    cudaGetSymbolAddress((void**)&mask1, g_mask1);

    // dynamic smem for the KT x HH weight tile (128 KB)
    const int tile_bytes = KT * HH * (int)sizeof(float);
    cudaFuncSetAttribute(k_gemm_sparse4,
                         cudaFuncAttributeMaxDynamicSharedMemorySize, tile_bytes);

    // output layout: spk0, spk1, spk2, mem0, mem1, mem2
    float* spk0 = out;
    float* spk1 = spk0 + (size_t)NS * HH;
    float* spk2 = spk1 + (size_t)NS * HH;
    float* mem0 = spk2 + (size_t)NS * 2;
    float* mem1 = mem0 + (size_t)NS * HH;
    float* mem2 = mem1 + (size_t)NS * HH;

    // weight transposes (K-major for row-gather)
    k_transpose<<<dim3(IN/32, HH/32), dim3(32, 8)>>>(W0, W0t, HH, IN);
    k_transpose<<<dim3(HH/32, HH/32), dim3(32, 8)>>>(W1, W1t, HH, HH);
    k_transpose<<<dim3(HH/32, 1),     dim3(32, 8)>>>(W2, W2t, 2,  HH);

    // pack input spikes to bitmasks (also does [B,T]->[T,B] reindex)
    k_pack_x<<<(NS * IN) / 256, 256>>>(x, maskX);

    // layer 0
    k_gemm_sparse4<<<NS/S3, 256, tile_bytes>>>(maskX, W0t, cur0, IN/32);
    k_scan<<<dim3(HH/256, BB), 256>>>(cur0, thr0, spk0, mem0, mask0, HH);

    // layer 1
    k_gemm_sparse4<<<NS/S3, 256, tile_bytes>>>(mask0, W1t, cur1, HH/32);
    k_scan<<<dim3(HH/256, BB), 256>>>(cur1, thr1, spk1, mem1, mask1, HH);

    // layer 2
    k_gemm2<<<NS/256, 256>>>(mask1, W2t, cur2);
    k_scan<<<dim3(1, BB), 32>>>(cur2, thr2, spk2, mem2, (unsigned int*)0, 2);
}

// round 3
// speedup vs baseline: 1.5504x; 1.0394x over previous
#include <cuda_runtime.h>

#define BB 256
#define TT 64
#define IN 512
#define HH 1024
#define NS (BB*TT)   /* 16384 samples, s = t*B + b */

// ---------------- scratch (__device__ globals; no allocs allowed) ----------------
__device__ unsigned int g_maskX[NS*16];        // 512-bit mask per sample
__device__ unsigned int g_mask0[NS*32];        // 1024-bit mask per sample
__device__ unsigned int g_mask1[NS*32];
__device__ float g_cur0[(size_t)NS*HH];        // 64 MB
__device__ float g_cur1[(size_t)NS*HH];        // 64 MB
__device__ float g_cur2[NS*2];
__device__ float g_W0t[IN*HH];                 // W0^T : [512][1024]
__device__ float g_W1t[HH*HH];                 // W1^T : [1024][1024]
__device__ float g_W2t[HH*2];                  // W2^T : [1024][2]

// ---------------- transpose: in[R][C] -> out[C][R] ----------------
__global__ void k_transpose(const float* __restrict__ in, float* __restrict__ out,
                            int R, int C) {
    __shared__ float tl[32][33];
    int c0 = blockIdx.x * 32, r0 = blockIdx.y * 32;
    int x = c0 + threadIdx.x;
    for (int j = 0; j < 32; j += 8) {
        int y = r0 + threadIdx.y + j;
        if (y < R && x < C) tl[threadIdx.y + j][threadIdx.x] = in[(size_t)y * C + x];
    }
    __syncthreads();
    int x2 = r0 + threadIdx.x;
    for (int j = 0; j < 32; j += 8) {
        int y2 = c0 + threadIdx.y + j;
        if (y2 < C && x2 < R) out[(size_t)y2 * R + x2] = tl[threadIdx.x][threadIdx.y + j];
    }
}

// ---------------- pack x [B,T,I] (batch-first) -> bitmask [s=(t*B+b)][16 words] ----
__global__ void k_pack_x(const float* __restrict__ x, unsigned int* __restrict__ mx) {
    int idx = blockIdx.x * blockDim.x + threadIdx.x;   // NS*IN threads
    int i = idx & (IN - 1);
    int s = idx >> 9;
    int t = s >> 8;          // s = t*B + b, B=256
    int b = s & (BB - 1);
    float v = x[((size_t)b * TT + t) * IN + i];
    unsigned bal = __ballot_sync(0xffffffffu, v != 0.0f);
    if ((i & 31) == 0) mx[s * 16 + (i >> 5)] = bal;
}

// ---------------- sparse binary GEMM (float2/thread, 512 thr, full H per CTA) -----
// cur[s][h] = sum_{k: bit set} Wt[k][h].  S samples per CTA share a [KT x H]
// dynamic-smem weight tile; k-skip and all branches are CTA-uniform.
#define S3 32
#define KT 32

extern __shared__ float dyn_tile[];   // KT * HH floats = 128 KB

__global__ __launch_bounds__(512, 1)
void k_gemm_sparse2(const unsigned int* __restrict__ masks,
                    const float* __restrict__ Wt,
                    float* __restrict__ cur, int KW /* = K/32 words */) {
    __shared__ unsigned int smask[S3];
    int tid = threadIdx.x;
    int s0 = blockIdx.x * S3;
    int c2 = tid * 2;                  // this thread's 2 h-columns

    float2 acc[S3];
#pragma unroll
    for (int s = 0; s < S3; ++s) acc[s] = make_float2(0.f, 0.f);

    for (int tw = 0; tw < KW; ++tw) {
        __syncthreads();                       // protect tile/smask from prev readers
        if (tid < S3) smask[tid] = masks[(size_t)(s0 + tid) * KW + tw];
        __syncthreads();

        unsigned int U = 0;                    // union of this k-tile's bits (uniform)
#pragma unroll
        for (int j = 0; j < S3; ++j) U |= smask[j];
        if (!U) continue;

        {   // stage only the rows any sample needs (uniform ffs loop)
            const float* Wb = Wt + (size_t)(tw * KT) * HH + c2;
            unsigned int u = U;
            while (u) {
                int r = __ffs(u) - 1; u &= u - 1;
                float2 w = *(const float2*)(Wb + (size_t)r * HH);
                *(float2*)&dyn_tile[r * HH + c2] = w;
            }
        }
        __syncthreads();

#pragma unroll
        for (int s = 0; s < S3; ++s) {
            unsigned int m = smask[s];
            while (m) {
                int k = __ffs(m) - 1; m &= m - 1;
                float2 w = *(const float2*)&dyn_tile[k * HH + c2];
                acc[s].x += w.x; acc[s].y += w.y;
            }
        }
    }
#pragma unroll
    for (int s = 0; s < S3; ++s)
        *(float2*)&cur[(size_t)(s0 + s) * HH + c2] = acc[s];
}

// ---------------- tiny output layer GEMM (H=2) ----------------
__global__ void k_gemm2(const unsigned int* __restrict__ masks,
                        const float* __restrict__ W2t, float* __restrict__ cur2) {
    int s = blockIdx.x * blockDim.x + threadIdx.x;
    if (s >= NS) return;
    float a0 = 0.0f, a1 = 0.0f;
    for (int w = 0; w < 32; ++w) {
        unsigned int m = masks[(size_t)s * 32 + w];
        while (m) {
            int k = __ffs(m) - 1; m &= m - 1;
            int kk = w * 32 + k;
            a0 += W2t[kk * 2];
            a1 += W2t[kk * 2 + 1];
        }
    }
    cur2[s * 2] = a0;
    cur2[s * 2 + 1] = a1;
}

// ---------------- leaky membrane scan over time (elementwise per (b,h)) ----------
__global__ void k_scan(const float* __restrict__ cur, const float* __restrict__ thr_p,
                       float* __restrict__ spk_out, float* __restrict__ mem_out,
                       unsigned int* __restrict__ mask_out, int Hdim) {
    int h = blockIdx.x * blockDim.x + threadIdx.x;
    int b = blockIdx.y;
    if (h >= Hdim) return;
    float thr = *thr_p;
    float mem = 0.0f;
    for (int t = 0; t < TT; ++t) {
        size_t idx = ((size_t)t * BB + b) * Hdim + h;
        float reset = (mem > thr) ? thr : 0.0f;        // uses mem from previous step
        mem = 0.5f * mem + cur[idx] - reset;
        float spk = (mem - thr) > 0.0f ? 1.0f : 0.0f;  // atan_spike forward = Heaviside
        spk_out[idx] = spk;
        mem_out[idx] = mem;
        if (mask_out) {
            unsigned bal = __ballot_sync(0xffffffffu, spk != 0.0f);
            if ((h & 31) == 0)
                mask_out[((size_t)t * BB + b) * (Hdim >> 5) + (h >> 5)] = bal;
        }
    }
}

// ---------------- launch ----------------
extern "C" void kernel_launch(void* const* d_in, const int* in_sizes, int n_in,
                              void* d_out, int out_size) {
    const float* x    = (const float*)d_in[0];
    const float* W0   = (const float*)d_in[1];
    const float* W1   = (const float*)d_in[2];
    const float* W2   = (const float*)d_in[3];
    const float* thr0 = (const float*)d_in[4];
    const float* thr1 = (const float*)d_in[5];
    const float* thr2 = (const float*)d_in[6];
    float* out = (float*)d_out;

    float *W0t, *W1t, *W2t, *cur0, *cur1, *cur2;
    unsigned int *maskX, *mask0, *mask1;
    cudaGetSymbolAddress((void**)&W0t,   g_W0t);
    cudaGetSymbolAddress((void**)&W1t,   g_W1t);
    cudaGetSymbolAddress((void**)&W2t,   g_W2t);
    cudaGetSymbolAddress((void**)&cur0,  g_cur0);
    cudaGetSymbolAddress((void**)&cur1,  g_cur1);
    cudaGetSymbolAddress((void**)&cur2,  g_cur2);
    cudaGetSymbolAddress((void**)&maskX, g_maskX);
    cudaGetSymbolAddress((void**)&mask0, g_mask0);
    cudaGetSymbolAddress((void**)&mask1, g_mask1);

    // dynamic smem for the KT x HH weight tile (128 KB)
    const int tile_bytes = KT * HH * (int)sizeof(float);
    cudaFuncSetAttribute(k_gemm_sparse2,
                         cudaFuncAttributeMaxDynamicSharedMemorySize, tile_bytes);

    // output layout: spk0, spk1, spk2, mem0, mem1, mem2
    float* spk0 = out;
    float* spk1 = spk0 + (size_t)NS * HH;
    float* spk2 = spk1 + (size_t)NS * HH;
    float* mem0 = spk2 + (size_t)NS * 2;
    float* mem1 = mem0 + (size_t)NS * HH;
    float* mem2 = mem1 + (size_t)NS * HH;

    // weight transposes (K-major for row-gather)
    k_transpose<<<dim3(IN/32, HH/32), dim3(32, 8)>>>(W0, W0t, HH, IN);
    k_transpose<<<dim3(HH/32, HH/32), dim3(32, 8)>>>(W1, W1t, HH, HH);
    k_transpose<<<dim3(HH/32, 1),     dim3(32, 8)>>>(W2, W2t, 2,  HH);

    // pack input spikes to bitmasks (also does [B,T]->[T,B] reindex)
    k_pack_x<<<(NS * IN) / 256, 256>>>(x, maskX);

    // layer 0
    k_gemm_sparse2<<<NS/S3, 512, tile_bytes>>>(maskX, W0t, cur0, IN/32);
    k_scan<<<dim3(HH/256, BB), 256>>>(cur0, thr0, spk0, mem0, mask0, HH);

    // layer 1
    k_gemm_sparse2<<<NS/S3, 512, tile_bytes>>>(mask0, W1t, cur1, HH/32);
    k_scan<<<dim3(HH/256, BB), 256>>>(cur1, thr1, spk1, mem1, mask1, HH);

    // layer 2
    k_gemm2<<<NS/256, 256>>>(mask1, W2t, cur2);
    k_scan<<<dim3(1, BB), 32>>>(cur2, thr2, spk2, mem2, (unsigned int*)0, 2);
}

// round 6
// speedup vs baseline: 5.5943x; 3.6084x over previous
#include <cuda_runtime.h>
#include <cuda_bf16.h>
#include <cstdint>

#define BB 256
#define TT 64
#define IN 512
#define HH 1024
#define NS (BB*TT)   /* 16384 samples, s = t*B + b */

// ---------------- scratch (__device__ globals; no allocs allowed) ----------------
__device__ unsigned int g_mask0[NS*32];        // layer-0 spike bitmasks
__device__ unsigned int g_mask1[NS*32];
__device__ float g_cur0[(size_t)NS*HH];        // 64 MB
__device__ float g_cur1[(size_t)NS*HH];        // 64 MB
__device__ float g_cur2[NS*2];
__device__ __nv_bfloat16 g_Abf[(size_t)NS*IN]; // input spikes as bf16 [s][i]
__device__ __nv_bfloat16 g_W0hi[HH*IN];        // bf16 split of W0 [h][i]
__device__ __nv_bfloat16 g_W0lo[HH*IN];
__device__ float g_W1t[HH*HH];                 // W1^T : [1024][1024]
__device__ float g_W2t[HH*2];                  // W2^T : [1024][2]

// ================= helpers =======================================================
__device__ __forceinline__ uint32_t smem_u32(const void* p) {
    uint32_t a;
    asm("{ .reg .u64 t; cvta.to.shared.u64 t, %1; cvt.u32.u64 %0, t; }" : "=r"(a) : "l"(p));
    return a;
}
__device__ __forceinline__ void cp_async16(uint32_t dst, const void* src) {
    asm volatile("cp.async.cg.shared.global [%0], [%1], 16;" :: "r"(dst), "l"(src));
}
__device__ __forceinline__ uint32_t lds32(uint32_t a) {
    uint32_t v;
    asm volatile("ld.shared.b32 %0, [%1];" : "=r"(v) : "r"(a));
    return v;
}
__device__ __forceinline__ void mma16816(float* c, const uint32_t* a, const uint32_t* b) {
    asm volatile(
        "mma.sync.aligned.m16n8k16.row.col.f32.bf16.bf16.f32 "
        "{%0,%1,%2,%3}, {%4,%5,%6,%7}, {%8,%9}, {%0,%1,%2,%3};"
        : "+f"(c[0]), "+f"(c[1]), "+f"(c[2]), "+f"(c[3])
        : "r"(a[0]), "r"(a[1]), "r"(a[2]), "r"(a[3]), "r"(b[0]), "r"(b[1]));
}

// ================= prep kernels ==================================================
// x [B][T][I] fp32 -> Abf [s=t*B+b][I] bf16 (binary, exact)
__global__ void k_convA(const float* __restrict__ x, __nv_bfloat16* __restrict__ A) {
    int p = blockIdx.x * blockDim.x + threadIdx.x;      // NS*IN/4 threads
    int i4 = p & 127;
    int s = p >> 7;
    int t = s >> 8, b = s & (BB - 1);
    float4 v = *(const float4*)(x + ((size_t)(b * TT + t) * IN + i4 * 4));
    __nv_bfloat162 lo = __floats2bfloat162_rn(v.x, v.y);
    __nv_bfloat162 hi = __floats2bfloat162_rn(v.z, v.w);
    uint2 o; o.x = *(uint32_t*)&lo; o.y = *(uint32_t*)&hi;
    *(uint2*)(A + (size_t)s * IN + i4 * 4) = o;
}
// W0 fp32 -> (hi, lo) bf16 split
__global__ void k_splitW(const float* __restrict__ W, __nv_bfloat16* __restrict__ Whi,
                         __nv_bfloat16* __restrict__ Wlo, int n) {
    int e = blockIdx.x * blockDim.x + threadIdx.x;
    if (e >= n) return;
    float w = W[e];
    __nv_bfloat16 h = __float2bfloat16(w);
    __nv_bfloat16 l = __float2bfloat16(w - __bfloat162float(h));
    Whi[e] = h; Wlo[e] = l;
}

// ---------------- transpose: in[R][C] -> out[C][R] ----------------
__global__ void k_transpose(const float* __restrict__ in, float* __restrict__ out,
                            int R, int C) {
    __shared__ float tl[32][33];
    int c0 = blockIdx.x * 32, r0 = blockIdx.y * 32;
    int x = c0 + threadIdx.x;
    for (int j = 0; j < 32; j += 8) {
        int y = r0 + threadIdx.y + j;
        if (y < R && x < C) tl[threadIdx.y + j][threadIdx.x] = in[(size_t)y * C + x];
    }
    __syncthreads();
    int x2 = r0 + threadIdx.x;
    for (int j = 0; j < 32; j += 8) {
        int y2 = c0 + threadIdx.y + j;
        if (y2 < C && x2 < R) out[(size_t)y2 * R + x2] = tl[threadIdx.x][threadIdx.y + j];
    }
}

// ================= layer-0 GEMM on legacy HMMA (mma.sync bf16) ===================
// cur0[16384 x 1024] = Abf[16384 x 512] @ (W0hi|W0lo)^T with fp32 accumulate.
// CTA tile 128x128, 8 warps (warp tile 32x64), K chunks of 64, double-buffered
// cp.async staging. K runs 8 chunks over W0hi then 8 over W0lo (split-bf16 exact).
#define KCH   64
#define LDAH  72                         /* padded row stride in halves */
#define ROWB  (LDAH*2)                   /* 144 bytes */
#define TILEB (128*ROWB)                 /* 18432 B per operand tile */
#define BUFB  (2*TILEB)                  /* A+B per buffer = 36864 B */

extern __shared__ char dynsm[];

__global__ __launch_bounds__(256, 2)
void k_gemm0_mma(const __nv_bfloat16* __restrict__ A,
                 const __nv_bfloat16* __restrict__ Whi,
                 const __nv_bfloat16* __restrict__ Wlo,
                 float* __restrict__ cur) {
    int tid = threadIdx.x;
    int wid = tid >> 5, lane = tid & 31;
    int g = lane >> 2, tig = lane & 3;           // mma groupID / thread-in-group
    int wm = wid & 3, wn = wid >> 2;             // warp grid 4(M) x 2(N)
    int m0 = blockIdx.x * 128;
    int n0 = blockIdx.y * 128;

    uint32_t smb = smem_u32(dynsm);

    float acc[2][8][4];
#pragma unroll
    for (int mi = 0; mi < 2; ++mi)
#pragma unroll
        for (int ni = 0; ni < 8; ++ni)
#pragma unroll
            for (int r = 0; r < 4; ++r) acc[mi][ni][r] = 0.0f;

    // stage chunk c into buffer buf (A tile + B tile, 4+4 cp.async per thread)
    auto stage = [&](int c, int buf) {
        const __nv_bfloat16* Wsrc = (c < 8) ? Whi : Wlo;
        int kcol = (c & 7) * KCH;
        uint32_t abase = smb + buf * BUFB;
        uint32_t bbase = abase + TILEB;
#pragma unroll
        for (int j = 0; j < 4; ++j) {
            int id = tid + j * 256;              // 1024 16B-chunks per tile
            int row = id >> 3, seg = id & 7;
            cp_async16(abase + row * ROWB + seg * 16,
                       A + (size_t)(m0 + row) * IN + kcol + seg * 8);
            cp_async16(bbase + row * ROWB + seg * 16,
                       Wsrc + (size_t)(n0 + row) * IN + kcol + seg * 8);
        }
        asm volatile("cp.async.commit_group;" ::: "memory");
    };

    stage(0, 0);

    for (int c = 0; c < 16; ++c) {
        int buf = c & 1;
        if (c + 1 < 16) {
            stage(c + 1, buf ^ 1);
            asm volatile("cp.async.wait_group 1;" ::: "memory");
        } else {
            asm volatile("cp.async.wait_group 0;" ::: "memory");
        }
        __syncthreads();

        uint32_t abase = smb + buf * BUFB;
        uint32_t bbase = abase + TILEB;
#pragma unroll
        for (int kk = 0; kk < 4; ++kk) {
            int ko = kk * 16;
            uint32_t a[2][4], b[8][2];
#pragma unroll
            for (int mi = 0; mi < 2; ++mi) {
                uint32_t base = abase + (uint32_t)(wm * 32 + mi * 16 + g) * ROWB
                              + (uint32_t)(ko + tig * 2) * 2;
                a[mi][0] = lds32(base);
                a[mi][1] = lds32(base + 8 * ROWB);
                a[mi][2] = lds32(base + 16);
                a[mi][3] = lds32(base + 8 * ROWB + 16);
            }
#pragma unroll
            for (int ni = 0; ni < 8; ++ni) {
                uint32_t base = bbase + (uint32_t)(wn * 64 + ni * 8 + g) * ROWB
                              + (uint32_t)(ko + tig * 2) * 2;
                b[ni][0] = lds32(base);
                b[ni][1] = lds32(base + 16);
            }
#pragma unroll
            for (int mi = 0; mi < 2; ++mi)
#pragma unroll
                for (int ni = 0; ni < 8; ++ni)
                    mma16816(acc[mi][ni], a[mi], b[ni]);
        }
        __syncthreads();
    }

    // epilogue: c0,c1 = (row g, cols tig*2..+1); c2,c3 = (row g+8, same cols)
#pragma unroll
    for (int mi = 0; mi < 2; ++mi) {
        int row = m0 + wm * 32 + mi * 16 + g;
#pragma unroll
        for (int ni = 0; ni < 8; ++ni) {
            int col = n0 + wn * 64 + ni * 8 + tig * 2;
            float2 lo = make_float2(acc[mi][ni][0], acc[mi][ni][1]);
            float2 hi = make_float2(acc[mi][ni][2], acc[mi][ni][3]);
            *(float2*)&cur[(size_t)row * HH + col] = lo;
            *(float2*)&cur[(size_t)(row + 8) * HH + col] = hi;
        }
    }
}

// ================= sparse binary GEMM for layer 1 ================================
#define S3 32
#define KT 32

__global__ __launch_bounds__(512, 1)
void k_gemm_sparse2(const unsigned int* __restrict__ masks,
                    const float* __restrict__ Wt,
                    float* __restrict__ cur, int KW /* = K/32 words */) {
    float* tile = (float*)dynsm;               // KT*HH floats = 128 KB
    __shared__ unsigned int smask[S3];
    int tid = threadIdx.x;
    int s0 = blockIdx.x * S3;
    int c2 = tid * 2;

    float2 acc[S3];
#pragma unroll
    for (int s = 0; s < S3; ++s) acc[s] = make_float2(0.f, 0.f);

    for (int tw = 0; tw < KW; ++tw) {
        __syncthreads();
        if (tid < S3) smask[tid] = masks[(size_t)(s0 + tid) * KW + tw];
        __syncthreads();

        unsigned int U = 0;
#pragma unroll
        for (int j = 0; j < S3; ++j) U |= smask[j];
        if (!U) continue;

        {
            const float* Wb = Wt + (size_t)(tw * KT) * HH + c2;
            unsigned int u = U;
            while (u) {
                int r = __ffs(u) - 1; u &= u - 1;
                float2 w = *(const float2*)(Wb + (size_t)r * HH);
                *(float2*)&tile[r * HH + c2] = w;
            }
        }
        __syncthreads();

#pragma unroll
        for (int s = 0; s < S3; ++s) {
            unsigned int m = smask[s];
            while (m) {
                int k = __ffs(m) - 1; m &= m - 1;
                float2 w = *(const float2*)&tile[k * HH + c2];
                acc[s].x += w.x; acc[s].y += w.y;
            }
        }
    }
#pragma unroll
    for (int s = 0; s < S3; ++s)
        *(float2*)&cur[(size_t)(s0 + s) * HH + c2] = acc[s];
}

// ================= tiny output layer GEMM (H=2) ==================================
__global__ void k_gemm2(const unsigned int* __restrict__ masks,
                        const float* __restrict__ W2t, float* __restrict__ cur2) {
    int s = blockIdx.x * blockDim.x + threadIdx.x;
    if (s >= NS) return;
    float a0 = 0.0f, a1 = 0.0f;
    for (int w = 0; w < 32; ++w) {
        unsigned int m = masks[(size_t)s * 32 + w];
        while (m) {
            int k = __ffs(m) - 1; m &= m - 1;
            int kk = w * 32 + k;
            a0 += W2t[kk * 2];
            a1 += W2t[kk * 2 + 1];
        }
    }
    cur2[s * 2] = a0;
    cur2[s * 2 + 1] = a1;
}

// ================= leaky membrane scan over time =================================
__global__ void k_scan(const float* __restrict__ cur, const float* __restrict__ thr_p,
                       float* __restrict__ spk_out, float* __restrict__ mem_out,
                       unsigned int* __restrict__ mask_out, int Hdim) {
    int h = blockIdx.x * blockDim.x + threadIdx.x;
    int b = blockIdx.y;
    if (h >= Hdim) return;
    float thr = *thr_p;
    float mem = 0.0f;
    for (int t = 0; t < TT; ++t) {
        size_t idx = ((size_t)t * BB + b) * Hdim + h;
        float reset = (mem > thr) ? thr : 0.0f;        // previous-step mem
        mem = 0.5f * mem + cur[idx] - reset;
        float spk = (mem - thr) > 0.0f ? 1.0f : 0.0f;  // Heaviside forward
        spk_out[idx] = spk;
        mem_out[idx] = mem;
        if (mask_out) {
            unsigned bal = __ballot_sync(0xffffffffu, spk != 0.0f);
            if ((h & 31) == 0)
                mask_out[((size_t)t * BB + b) * (Hdim >> 5) + (h >> 5)] = bal;
        }
    }
}

// ================= launch ========================================================
extern "C" void kernel_launch(void* const* d_in, const int* in_sizes, int n_in,
                              void* d_out, int out_size) {
    const float* x    = (const float*)d_in[0];
    const float* W0   = (const float*)d_in[1];
    const float* W1   = (const float*)d_in[2];
    const float* W2   = (const float*)d_in[3];
    const float* thr0 = (const float*)d_in[4];
    const float* thr1 = (const float*)d_in[5];
    const float* thr2 = (const float*)d_in[6];
    float* out = (float*)d_out;

    float *W1t, *W2t, *cur0, *cur1, *cur2;
    __nv_bfloat16 *Abf, *W0hi, *W0lo;
    unsigned int *mask0, *mask1;
    cudaGetSymbolAddress((void**)&W1t,   g_W1t);
    cudaGetSymbolAddress((void**)&W2t,   g_W2t);
    cudaGetSymbolAddress((void**)&cur0,  g_cur0);
    cudaGetSymbolAddress((void**)&cur1,  g_cur1);
    cudaGetSymbolAddress((void**)&cur2,  g_cur2);
    cudaGetSymbolAddress((void**)&Abf,   g_Abf);
    cudaGetSymbolAddress((void**)&W0hi,  g_W0hi);
    cudaGetSymbolAddress((void**)&W0lo,  g_W0lo);
    cudaGetSymbolAddress((void**)&mask0, g_mask0);
    cudaGetSymbolAddress((void**)&mask1, g_mask1);

    const int gemm0_smem  = 2 * BUFB;                           // 73,728 B
    const int sparse_smem = KT * HH * (int)sizeof(float);       // 128 KB
    cudaFuncSetAttribute(k_gemm0_mma,
                         cudaFuncAttributeMaxDynamicSharedMemorySize, gemm0_smem);
    cudaFuncSetAttribute(k_gemm_sparse2,
                         cudaFuncAttributeMaxDynamicSharedMemorySize, sparse_smem);

    // output layout: spk0, spk1, spk2, mem0, mem1, mem2
    float* spk0 = out;
    float* spk1 = spk0 + (size_t)NS * HH;
    float* spk2 = spk1 + (size_t)NS * HH;
    float* mem0 = spk2 + (size_t)NS * 2;
    float* mem1 = mem0 + (size_t)NS * HH;
    float* mem2 = mem1 + (size_t)NS * HH;

    // prep
    k_convA<<<(NS * IN / 4) / 256, 256>>>(x, Abf);
    k_splitW<<<(HH * IN) / 256, 256>>>(W0, W0hi, W0lo, HH * IN);
    k_transpose<<<dim3(HH/32, HH/32), dim3(32, 8)>>>(W1, W1t, HH, HH);
    k_transpose<<<dim3(HH/32, 1),     dim3(32, 8)>>>(W2, W2t, 2,  HH);

    // layer 0: tensor-core split-bf16 GEMM (legacy mma.sync, sm_103-safe)
    k_gemm0_mma<<<dim3(NS/128, HH/128), 256, gemm0_smem>>>(Abf, W0hi, W0lo, cur0);
    k_scan<<<dim3(HH/256, BB), 256>>>(cur0, thr0, spk0, mem0, mask0, HH);

    // layer 1: sparse (hidden firing ~0.4%)
    k_gemm_sparse2<<<NS/S3, 512, sparse_smem>>>(mask0, W1t, cur1, HH/32);
    k_scan<<<dim3(HH/256, BB), 256>>>(cur1, thr1, spk1, mem1, mask1, HH);

    // layer 2
    k_gemm2<<<NS/256, 256>>>(mask1, W2t, cur2);
    k_scan<<<dim3(1, BB), 32>>>(cur2, thr2, spk2, mem2, (unsigned int*)0, 2);
}